// round 2
// baseline (speedup 1.0000x reference)
#include <cuda_runtime.h>

#define HW   262144      // 512*512
#define NHW  4194304     // 16*512*512
#define NROW 512
#define WPR  16          // 32-bit words per row
#define PITCH 17         // padded smem pitch (conflict-free)

// ---------------- device globals (no allocations allowed) ----------------
__device__ double g_mean[32];
__device__ double g_std[32];
__device__ unsigned g_bm[2 * 16 * 8192];   // [branch][n][row*16+w] bitmaps

// ---------------- helpers ----------------
struct DF { float hi, lo; };

__device__ __forceinline__ DF df_add(DF a, float b) {
    float s  = __fadd_rn(a.hi, b);
    float bv = __fsub_rn(s, a.hi);
    float err = __fadd_rn(__fsub_rn(a.hi, __fsub_rn(s, bv)), __fsub_rn(b, bv));
    float lo = __fadd_rn(a.lo, err);
    float hi = __fadd_rn(s, lo);
    float lo2 = __fadd_rn(__fsub_rn(s, hi), lo);
    DF r; r.hi = hi; r.lo = lo2; return r;
}
__device__ __forceinline__ DF df_add2(DF a, DF b) {
    float s  = __fadd_rn(a.hi, b.hi);
    float bv = __fsub_rn(s, a.hi);
    float err = __fadd_rn(__fsub_rn(a.hi, __fsub_rn(s, bv)), __fsub_rn(b.hi, bv));
    float lo = __fadd_rn(__fadd_rn(a.lo, b.lo), err);
    float hi = __fadd_rn(s, lo);
    float lo2 = __fadd_rn(__fsub_rn(s, hi), lo);
    DF r; r.hi = hi; r.lo = lo2; return r;
}

__device__ __forceinline__ float sigm(float x) {
    return 1.0f / (1.0f + expf(-x));
}

// ---------------- kernel 1: per-image mean / std ----------------
__global__ __launch_bounds__(512) void stats_kernel(const float* __restrict__ thick,
                                                    const float* __restrict__ thin) {
    int img = blockIdx.x;                       // 0..31 ; branch = img>>4
    const float* src = ((img >> 4) ? thin : thick) + (img & 15) * HW;
    const float4* s4 = (const float4*)src;

    DF s; s.hi = 0.f; s.lo = 0.f;
    DF q; q.hi = 0.f; q.lo = 0.f;
    for (int i = threadIdx.x; i < HW / 4; i += 512) {
        float4 v = s4[i];
        float p0 = sigm(v.x), p1 = sigm(v.y), p2 = sigm(v.z), p3 = sigm(v.w);
        s = df_add(s, p0); s = df_add(s, p1); s = df_add(s, p2); s = df_add(s, p3);
        q = df_add(q, p0 * p0); q = df_add(q, p1 * p1);
        q = df_add(q, p2 * p2); q = df_add(q, p3 * p3);
    }

    __shared__ DF red[512];
    __shared__ double s_tot;
    red[threadIdx.x] = s;
    __syncthreads();
    for (int o = 256; o; o >>= 1) {
        if (threadIdx.x < o) red[threadIdx.x] = df_add2(red[threadIdx.x], red[threadIdx.x + o]);
        __syncthreads();
    }
    if (threadIdx.x == 0) s_tot = (double)red[0].hi + (double)red[0].lo;
    __syncthreads();
    red[threadIdx.x] = q;
    __syncthreads();
    for (int o = 256; o; o >>= 1) {
        if (threadIdx.x < o) red[threadIdx.x] = df_add2(red[threadIdx.x], red[threadIdx.x + o]);
        __syncthreads();
    }
    if (threadIdx.x == 0) {
        double S = s_tot;
        double Q = (double)red[0].hi + (double)red[0].lo;
        double mean = S / (double)HW;
        double var = Q / (double)HW - mean * mean;
        if (var < 0.0) var = 0.0;
        g_mean[img] = mean;
        g_std[img]  = sqrt(var);
    }
}

// ---------------- kernel 2: threshold select + flood fill ----------------
__global__ __launch_bounds__(512) void flood_kernel(const float* __restrict__ thick,
                                                    const float* __restrict__ thin) {
    __shared__ unsigned sm[NROW * PITCH];   // rec bitmap (also used for mask staging)
    __shared__ int ired[512];
    __shared__ float s_T[2];
    __shared__ int s_changed;

    int img = blockIdx.x;
    const float* src = ((img >> 4) ? thin : thick) + (img & 15) * HW;
    int tid = threadIdx.x, lane = tid & 31, warp = tid >> 5;

    double mean = g_mean[img], sd = g_std[img];
    float fm  = (img >> 4) ? 4.0f : 2.0f;
    float TmF = (float)(mean + (double)fm * sd);
    float TmH = (float)(mean + 0.5 * (double)fm * sd);
    float TkF = (float)(mean + 0.5 * sd);
    float TkH = (float)(mean + 0.25 * sd);

    // ---- pass 1: counts for empty-fallback ----
    int cm = 0, ck = 0;
    for (int w = warp; w < 8192; w += 16) {
        float p = sigm(src[(w << 5) + lane]);
        cm += (p > TmF);
        ck += (p > TkF);
    }
    ired[tid] = cm; __syncthreads();
    for (int o = 256; o; o >>= 1) { if (tid < o) ired[tid] += ired[tid + o]; __syncthreads(); }
    if (tid == 0) s_T[0] = ired[0] ? TmF : TmH;
    __syncthreads();
    ired[tid] = ck; __syncthreads();
    for (int o = 256; o; o >>= 1) { if (tid < o) ired[tid] += ired[tid + o]; __syncthreads(); }
    if (tid == 0) s_T[1] = ired[0] ? TkF : TkH;
    __syncthreads();
    float Tm = s_T[0], Tk = s_T[1];

    // ---- pass 2: mask bitmap via ballot ----
    for (int w = warp; w < 8192; w += 16) {
        float p = sigm(src[(w << 5) + lane]);
        unsigned b = __ballot_sync(0xffffffffu, p > Tk);
        if (lane == 0) sm[(w >> 4) * PITCH + (w & 15)] = b;
    }
    __syncthreads();
    unsigned m[WPR], cur[WPR];
    #pragma unroll
    for (int w = 0; w < WPR; w++) m[w] = sm[tid * PITCH + w];
    __syncthreads();

    // ---- pass 3: marker bitmap (initial rec) ----
    for (int w = warp; w < 8192; w += 16) {
        float p = sigm(src[(w << 5) + lane]);
        unsigned b = __ballot_sync(0xffffffffu, p > Tm);
        if (lane == 0) sm[(w >> 4) * PITCH + (w & 15)] = b;
    }
    __syncthreads();
    #pragma unroll
    for (int w = 0; w < WPR; w++) cur[w] = sm[tid * PITCH + w] & m[w];
    // keep smem consistent with cur (marker is a subset of mask anyway)
    #pragma unroll
    for (int w = 0; w < WPR; w++) sm[tid * PITCH + w] = cur[w];
    __syncthreads();

    int r = tid;
    for (int it = 0; it < 1536; ++it) {
        if (tid == 0) s_changed = 0;
        __syncthreads();

        unsigned t[WPR];
        // vertical OR (Gauss-Seidel through smem), then AND mask
        #pragma unroll
        for (int w = 0; w < WPR; w++) {
            unsigned v = cur[w];
            if (r > 0)   v |= sm[(r - 1) * PITCH + w];
            if (r < 511) v |= sm[(r + 1) * PITCH + w];
            t[w] = v & m[w];
        }
        // horizontal run-fill up (toward MSB) — 512-bit carry add
        unsigned c = 0;
        #pragma unroll
        for (int w = 0; w < WPR; w++) {
            unsigned long long a = (unsigned long long)m[w] + (unsigned long long)t[w] + c;
            unsigned sum = (unsigned)a; c = (unsigned)(a >> 32);
            t[w] |= (m[w] ^ sum) & m[w];
        }
        // horizontal run-fill down (toward LSB) — bit-reversed add
        c = 0;
        #pragma unroll
        for (int k = 0; k < WPR; k++) {
            int w = WPR - 1 - k;
            unsigned rm = __brev(m[w]), rs = __brev(t[w]);
            unsigned long long a = (unsigned long long)rm + (unsigned long long)rs + c;
            unsigned sum = (unsigned)a; c = (unsigned)(a >> 32);
            t[w] |= __brev((rm ^ sum) & rm);
        }

        unsigned ch = 0;
        #pragma unroll
        for (int w = 0; w < WPR; w++) ch |= t[w] ^ cur[w];
        if (ch) {
            #pragma unroll
            for (int w = 0; w < WPR; w++) { sm[r * PITCH + w] = t[w]; cur[w] = t[w]; }
            s_changed = 1;
        }
        __syncthreads();
        if (!s_changed) break;
    }

    unsigned* dst = g_bm + img * 8192 + r * 16;
    #pragma unroll
    for (int w = 0; w < WPR; w++) dst[w] = cur[w];
}

// ---------------- kernel 3: fuse (OR of the two branches) ----------------
__global__ void fuse_kernel(float* __restrict__ outf) {
    int i = blockIdx.x * blockDim.x + threadIdx.x;   // float4 index over NHW/4
    if (i >= NHW / 4) return;
    int pix = i << 2;
    int wg = pix >> 5;                               // global word index 0..131071
    unsigned u = g_bm[wg] | g_bm[131072 + wg];
    int sh = pix & 31;
    float4 f;
    f.x = (float)((u >> sh) & 1u);
    f.y = (float)((u >> (sh + 1)) & 1u);
    f.z = (float)((u >> (sh + 2)) & 1u);
    f.w = (float)((u >> (sh + 3)) & 1u);
    ((float4*)outf)[i] = f;
}

// ---------------- launch ----------------
extern "C" void kernel_launch(void* const* d_in, const int* in_sizes, int n_in,
                              void* d_out, int out_size) {
    const float* thick = (const float*)d_in[0];
    const float* thin  = (const float*)d_in[1];
    float* out = (float*)d_out;

    cudaMemcpyAsync(out,        thick, (size_t)NHW * sizeof(float), cudaMemcpyDeviceToDevice);
    cudaMemcpyAsync(out + NHW,  thin,  (size_t)NHW * sizeof(float), cudaMemcpyDeviceToDevice);

    stats_kernel<<<32, 512>>>(thick, thin);
    flood_kernel<<<32, 512>>>(thick, thin);
    fuse_kernel<<<(NHW / 4 + 255) / 256, 256>>>(out + 2 * NHW);
}

// round 3
// speedup vs baseline: 4.7833x; 4.7833x over previous
#include <cuda_runtime.h>

#define HW    262144      // 512*512
#define NHW   4194304     // 16*512*512
#define NROW  512
#define WPRL  8           // 64-bit words per row
#define SPITCH 9          // smem pitch in u64 (conflict-free)

// ---------------- device globals (no allocations allowed) ----------------
__device__ double g_psum[1024];          // [img(32)][chunk(32)]
__device__ double g_pssq[1024];
__device__ float  g_thr[128];            // [img][ TmF,TmH,TkF,TkH ]
__device__ unsigned long long g_mkF[32 * 4096];  // marker @ full factor
__device__ unsigned long long g_mkH[32 * 4096];  // marker @ half factor
__device__ unsigned long long g_msF[32 * 4096];  // mask   @ 0.5
__device__ unsigned long long g_msH[32 * 4096];  // mask   @ 0.25
__device__ int g_pcntM[512];             // [img][chunk(16)] marker-full popcounts
__device__ int g_pcntK[512];             // mask-full popcounts
__device__ unsigned long long g_bm[32 * 4096];   // final rec bitmaps

__device__ __forceinline__ float sigm(float x) {
    return 1.0f / (1.0f + expf(-x));
}

// 512-bit add: x = a + b (little-endian u64 words)
__device__ __forceinline__ void add512(unsigned long long* x,
                                       const unsigned long long* a,
                                       const unsigned long long* b) {
    asm("add.cc.u64  %0, %8,  %16;\n\t"
        "addc.cc.u64 %1, %9,  %17;\n\t"
        "addc.cc.u64 %2, %10, %18;\n\t"
        "addc.cc.u64 %3, %11, %19;\n\t"
        "addc.cc.u64 %4, %12, %20;\n\t"
        "addc.cc.u64 %5, %13, %21;\n\t"
        "addc.cc.u64 %6, %14, %22;\n\t"
        "addc.cc.u64 %7, %15, %23;\n\t"
        : "=l"(x[0]), "=l"(x[1]), "=l"(x[2]), "=l"(x[3]),
          "=l"(x[4]), "=l"(x[5]), "=l"(x[6]), "=l"(x[7])
        : "l"(a[0]), "l"(a[1]), "l"(a[2]), "l"(a[3]),
          "l"(a[4]), "l"(a[5]), "l"(a[6]), "l"(a[7]),
          "l"(b[0]), "l"(b[1]), "l"(b[2]), "l"(b[3]),
          "l"(b[4]), "l"(b[5]), "l"(b[6]), "l"(b[7]));
}

// Horizontal run-fill (both directions) of seed set t within mask m.
// rm[k] must be __brevll(m[7-k]) (precomputed). Requires t subset-of m.
__device__ __forceinline__ void fill_row(unsigned long long* t,
                                         const unsigned long long* m,
                                         const unsigned long long* rm) {
    unsigned long long x[8];
    add512(x, m, t);
    #pragma unroll
    for (int w = 0; w < 8; w++) t[w] |= (m[w] ^ x[w]) & m[w];
    unsigned long long rt[8];
    #pragma unroll
    for (int k = 0; k < 8; k++) rt[k] = __brevll(t[7 - k]);
    add512(x, rm, rt);
    #pragma unroll
    for (int k = 0; k < 8; k++) t[7 - k] |= __brevll((rm[k] ^ x[k]) & rm[k]);
}

// ---------------- kernel A: sigmoid stats + logit copy ----------------
// 1024 CTAs x 256 thr : img = blk>>5 (0..31), chunk = blk&31 (8192 px each)
__global__ __launch_bounds__(256) void statsA_kernel(const float* __restrict__ thick,
                                                     const float* __restrict__ thin,
                                                     float* __restrict__ out) {
    int img = blockIdx.x >> 5;
    int chunk = blockIdx.x & 31;
    const float* src = ((img >> 4) ? thin : thick) + (img & 15) * HW + chunk * 8192;
    float* dst = out + img * HW + chunk * 8192;   // out = [thick(16)|thin(16)]
    const float4* s4 = (const float4*)src;
    float4* d4 = (float4*)dst;

    double ds = 0.0, dq = 0.0;
    #pragma unroll
    for (int i = 0; i < 8; i++) {
        int idx = threadIdx.x + i * 256;
        float4 v = s4[idx];
        d4[idx] = v;                               // logit passthrough copy
        float p0 = sigm(v.x), p1 = sigm(v.y), p2 = sigm(v.z), p3 = sigm(v.w);
        float s = (p0 + p1) + (p2 + p3);
        float q = (p0 * p0 + p1 * p1) + (p2 * p2 + p3 * p3);
        ds += (double)s;
        dq += (double)q;
    }

    __shared__ double red[256];
    red[threadIdx.x] = ds;
    __syncthreads();
    for (int o = 128; o; o >>= 1) {
        if (threadIdx.x < o) red[threadIdx.x] += red[threadIdx.x + o];
        __syncthreads();
    }
    if (threadIdx.x == 0) g_psum[blockIdx.x] = red[0];
    __syncthreads();
    red[threadIdx.x] = dq;
    __syncthreads();
    for (int o = 128; o; o >>= 1) {
        if (threadIdx.x < o) red[threadIdx.x] += red[threadIdx.x + o];
        __syncthreads();
    }
    if (threadIdx.x == 0) g_pssq[blockIdx.x] = red[0];
}

// ---------------- kernel B: finalize thresholds ----------------
__global__ void finalize_kernel() {
    int img = threadIdx.x;
    if (img >= 32) return;
    double S = 0.0, Q = 0.0;
    for (int c = 0; c < 32; c++) { S += g_psum[img * 32 + c]; Q += g_pssq[img * 32 + c]; }
    double mean = S / (double)HW;
    double var = Q / (double)HW - mean * mean;
    if (var < 0.0) var = 0.0;
    double sd = sqrt(var);
    double fm = (img >> 4) ? 4.0 : 2.0;
    g_thr[img * 4 + 0] = (float)(mean + fm * sd);
    g_thr[img * 4 + 1] = (float)(mean + 0.5 * fm * sd);
    g_thr[img * 4 + 2] = (float)(mean + 0.5 * sd);
    g_thr[img * 4 + 3] = (float)(mean + 0.25 * sd);
}

// ---------------- kernel C: build candidate bitmaps + counts ----------------
// 512 CTAs x 256 thr : img = blk>>4, chunk = blk&15 (512 words of 32px each)
__global__ __launch_bounds__(256) void bitmap_kernel(const float* __restrict__ thick,
                                                     const float* __restrict__ thin) {
    int img = blockIdx.x >> 4;
    int chunk = blockIdx.x & 15;
    const float* src = ((img >> 4) ? thin : thick) + (img & 15) * HW;
    int lane = threadIdx.x & 31, warp = threadIdx.x >> 5;

    float TmF = g_thr[img * 4 + 0], TmH = g_thr[img * 4 + 1];
    float TkF = g_thr[img * 4 + 2], TkH = g_thr[img * 4 + 3];

    unsigned* mkF = (unsigned*)g_mkF + img * 8192;
    unsigned* mkH = (unsigned*)g_mkH + img * 8192;
    unsigned* msF = (unsigned*)g_msF + img * 8192;
    unsigned* msH = (unsigned*)g_msH + img * 8192;

    int cm = 0, ck = 0;
    int wbase = chunk * 512;
    for (int w = wbase + warp; w < wbase + 512; w += 8) {
        float p = sigm(src[(w << 5) + lane]);
        unsigned b0 = __ballot_sync(0xffffffffu, p > TmF);
        unsigned b1 = __ballot_sync(0xffffffffu, p > TmH);
        unsigned b2 = __ballot_sync(0xffffffffu, p > TkF);
        unsigned b3 = __ballot_sync(0xffffffffu, p > TkH);
        if (lane == 0) {
            mkF[w] = b0; mkH[w] = b1; msF[w] = b2; msH[w] = b3;
            cm += __popc(b0); ck += __popc(b2);
        }
    }
    __shared__ int sM[8], sK[8];
    if (lane == 0) { sM[warp] = cm; sK[warp] = ck; }
    __syncthreads();
    if (threadIdx.x == 0) {
        int tm = 0, tk = 0;
        for (int i = 0; i < 8; i++) { tm += sM[i]; tk += sK[i]; }
        g_pcntM[img * 16 + chunk] = tm;
        g_pcntK[img * 16 + chunk] = tk;
    }
}

// ---------------- kernel D: flood fill (32 CTAs x 512 thr) ----------------
__global__ __launch_bounds__(512) void flood_kernel() {
    __shared__ unsigned long long sm[NROW * SPITCH];   // 36864 B
    __shared__ int s_sel[2];
    __shared__ int s_changed;

    int img = blockIdx.x;
    int tid = threadIdx.x;
    int r = tid;

    if (tid == 0) {
        int cm = 0, ck = 0;
        for (int c = 0; c < 16; c++) {
            cm += g_pcntM[img * 16 + c];
            ck += g_pcntK[img * 16 + c];
        }
        s_sel[0] = (cm > 0);
        s_sel[1] = (ck > 0);
    }
    __syncthreads();

    const unsigned long long* mk = (s_sel[0] ? g_mkF : g_mkH) + img * 4096 + r * WPRL;
    const unsigned long long* ms = (s_sel[1] ? g_msF : g_msH) + img * 4096 + r * WPRL;

    unsigned long long m[8], rm[8], cur[8];
    #pragma unroll
    for (int w = 0; w < 8; w++) m[w] = ms[w];
    #pragma unroll
    for (int k = 0; k < 8; k++) rm[k] = __brevll(m[7 - k]);
    #pragma unroll
    for (int w = 0; w < 8; w++) cur[w] = mk[w] & m[w];

    fill_row(cur, m, rm);   // make initial state fill-stable
    #pragma unroll
    for (int w = 0; w < 8; w++) sm[r * SPITCH + w] = cur[w];
    __syncthreads();

    for (int it = 0; it < 1536; ++it) {
        if (tid == 0) s_changed = 0;
        __syncthreads();

        unsigned long long t[8];
        unsigned long long diff = 0ull;
        #pragma unroll
        for (int w = 0; w < 8; w++) {
            unsigned long long v = cur[w];
            if (r > 0)   v |= sm[(r - 1) * SPITCH + w];
            if (r < 511) v |= sm[(r + 1) * SPITCH + w];
            t[w] = v & m[w];
            diff |= t[w] ^ cur[w];
        }
        if (diff) {
            fill_row(t, m, rm);
            #pragma unroll
            for (int w = 0; w < 8; w++) { cur[w] = t[w]; sm[r * SPITCH + w] = t[w]; }
            s_changed = 1;
        }
        __syncthreads();
        if (!s_changed) break;
    }

    unsigned long long* dst = g_bm + img * 4096 + r * WPRL;
    #pragma unroll
    for (int w = 0; w < 8; w++) dst[w] = cur[w];
}

// ---------------- kernel E: fuse (OR thick/thin bitmaps -> floats) ----------------
__global__ void fuse_kernel(float* __restrict__ outf) {
    int i = blockIdx.x * blockDim.x + threadIdx.x;   // float4 index over NHW/4
    if (i >= NHW / 4) return;
    const unsigned* bm = (const unsigned*)g_bm;
    int pix = i << 2;
    int wg = pix >> 5;                               // word idx 0..131071 (thick block)
    unsigned u = bm[wg] | bm[131072 + wg];
    int sh = pix & 31;
    float4 f;
    f.x = (float)((u >> sh) & 1u);
    f.y = (float)((u >> (sh + 1)) & 1u);
    f.z = (float)((u >> (sh + 2)) & 1u);
    f.w = (float)((u >> (sh + 3)) & 1u);
    ((float4*)outf)[i] = f;
}

// ---------------- launch ----------------
extern "C" void kernel_launch(void* const* d_in, const int* in_sizes, int n_in,
                              void* d_out, int out_size) {
    const float* thick = (const float*)d_in[0];
    const float* thin  = (const float*)d_in[1];
    float* out = (float*)d_out;

    statsA_kernel<<<1024, 256>>>(thick, thin, out);
    finalize_kernel<<<1, 32>>>();
    bitmap_kernel<<<512, 256>>>(thick, thin);
    flood_kernel<<<32, 512>>>();
    fuse_kernel<<<(NHW / 4 + 255) / 256, 256>>>(out + 2 * NHW);
}